// round 9
// baseline (speedup 1.0000x reference)
#include <cuda_runtime.h>
#include <cuda_bf16.h>
#include <stdint.h>
#include <string.h>

// Problem constants
#define BDIM   1024
#define NSEQ   2304
#define NB     4
#define NH     16
#define HD     64
#define MROWS  (NB*NSEQ)      // 9216
#define HPATCH 48

// ---------------- scratch (static device globals; no allocation) -------------
__device__ float g_q [(size_t)NB*NH*NSEQ*HD];     // pre-rope  [b,h,n,d]
__device__ float g_k [(size_t)NB*NH*NSEQ*HD];
__device__ float g_v [(size_t)NB*NH*NSEQ*HD];
__device__ float g_q2[(size_t)NB*NH*NSEQ*HD];     // post-rope [b,h,n,d]
__device__ float g_k2[(size_t)NB*NH*NSEQ*HD];
__device__ float g_attn[(size_t)NB*NSEQ*BDIM];    // [b,n,D] attention output
// packed bf16-pair buffers (hi / lo splits), reused across projections
__device__ uint32_t g_xh[(size_t)MROWS*BDIM/2];   // GEMM input X, hi
__device__ uint32_t g_xl[(size_t)MROWS*BDIM/2];   // GEMM input X, lo
__device__ uint32_t g_wh[(size_t)BDIM*BDIM/2];    // weight, hi
__device__ uint32_t g_wl[(size_t)BDIM*BDIM/2];    // weight, lo

// ---------------- bf16 helpers -----------------------------------------------
__device__ __forceinline__ uint32_t pack2(float a, float b) {
    __nv_bfloat16 ha = __float2bfloat16_rn(a);
    __nv_bfloat16 hb = __float2bfloat16_rn(b);
    uint16_t ra, rb;
    memcpy(&ra, &ha, 2); memcpy(&rb, &hb, 2);
    return (uint32_t)ra | ((uint32_t)rb << 16);
}
__device__ __forceinline__ float lo_of(float x) {
    return x - __bfloat162float(__float2bfloat16_rn(x));
}
__device__ __forceinline__ float ex2_approx(float x) {
    float r;
    asm("ex2.approx.ftz.f32 %0, %1;" : "=f"(r) : "f"(x));
    return r;
}

__device__ __forceinline__ void mma_bf16(float acc[4],
    uint32_t a0, uint32_t a1, uint32_t a2, uint32_t a3,
    uint32_t b0, uint32_t b1)
{
    asm volatile(
        "mma.sync.aligned.m16n8k16.row.col.f32.bf16.bf16.f32 "
        "{%0,%1,%2,%3}, {%4,%5,%6,%7}, {%8,%9}, {%0,%1,%2,%3};"
        : "+f"(acc[0]), "+f"(acc[1]), "+f"(acc[2]), "+f"(acc[3])
        : "r"(a0), "r"(a1), "r"(a2), "r"(a3), "r"(b0), "r"(b1));
}

// =============================================================================
// split: f32 -> packed bf16 hi/lo pairs (uint2 = 4 bf16)
// =============================================================================
__global__ __launch_bounds__(256)
void split_kernel(const float4* __restrict__ src, uint2* __restrict__ hi,
                  uint2* __restrict__ lo, int n4)
{
    int i = blockIdx.x * blockDim.x + threadIdx.x;
    if (i >= n4) return;
    float4 v = src[i];
    uint2 h, l;
    h.x = pack2(v.x, v.y);
    h.y = pack2(v.z, v.w);
    l.x = pack2(lo_of(v.x), lo_of(v.y));
    l.y = pack2(lo_of(v.z), lo_of(v.w));
    hi[i] = h;
    lo[i] = l;
}

// =============================================================================
// Projection GEMM (bf16x3, pre-split inputs): C[m][n] = X[m][:]·W[n][:] + b[n]
// 128x128 block, 256 threads, BK=32, warp tile 64x32. Inputs are packed bf16
// hi/lo pair arrays (k-major, 512 words per row). Smem 20-word row stride.
// Identical mma/fragment/epilogue structure to the round-7 verified kernel;
// only the load stage changed (straight uint4 copies, no conversion).
// =============================================================================
template<int HEADSPLIT>
__global__ __launch_bounds__(256, 2)
void proj_mma3s(const uint4* __restrict__ Xh, const uint4* __restrict__ Xl,
                const uint4* __restrict__ Wh, const uint4* __restrict__ Wl,
                const float* __restrict__ bias, float* __restrict__ out)
{
    __shared__ uint32_t Xh32[128*20], Xl32[128*20];
    __shared__ uint32_t Wh32[128*20], Wl32[128*20];

    const int tid   = threadIdx.x;
    const int lane  = tid & 31;
    const int wid   = tid >> 5;
    const int warpM = wid & 1;
    const int warpN = wid >> 1;
    const int c     = lane & 3;
    const int lr    = lane >> 2;
    const int m0 = blockIdx.y * 128;
    const int n0 = blockIdx.x * 128;
    const int RW = BDIM/8;            // 128 uint4 per row

    float acc[4][4][4];
    #pragma unroll
    for (int a = 0; a < 4; a++)
        #pragma unroll
        for (int b = 0; b < 4; b++)
            #pragma unroll
            for (int d = 0; d < 4; d++) acc[a][b][d] = 0.f;

    for (int k0 = 0; k0 < BDIM; k0 += 32) {
        const int kq4 = k0 >> 3;      // uint4 offset within row
        __syncthreads();
        #pragma unroll
        for (int s = 0; s < 2; s++) {
            int idx = tid + s*256;    // 0..511 : r = idx>>2, q = idx&3
            int r = idx >> 2, q = idx & 3;
            size_t g = (size_t)(m0 + r)*RW + kq4 + q;
            size_t gw = (size_t)(n0 + r)*RW + kq4 + q;
            *(uint4*)&Xh32[r*20 + q*4] = Xh[g];
            *(uint4*)&Xl32[r*20 + q*4] = Xl[g];
            *(uint4*)&Wh32[r*20 + q*4] = Wh[gw];
            *(uint4*)&Wl32[r*20 + q*4] = Wl[gw];
        }
        __syncthreads();

        #pragma unroll
        for (int kt = 0; kt < 2; kt++) {
            uint32_t ah[4][4], al[4][4];
            #pragma unroll
            for (int mt = 0; mt < 4; mt++) {
                int rA = warpM*64 + mt*16 + lr;
                int w  = rA*20 + kt*8 + c;
                ah[mt][0] = Xh32[w];        ah[mt][1] = Xh32[w + 8*20];
                ah[mt][2] = Xh32[w + 4];    ah[mt][3] = Xh32[w + 8*20 + 4];
                al[mt][0] = Xl32[w];        al[mt][1] = Xl32[w + 8*20];
                al[mt][2] = Xl32[w + 4];    al[mt][3] = Xl32[w + 8*20 + 4];
            }
            uint32_t bh[4][2], bl[4][2];
            #pragma unroll
            for (int nt = 0; nt < 4; nt++) {
                int nB = warpN*32 + nt*8 + lr;
                int w  = nB*20 + kt*8 + c;
                bh[nt][0] = Wh32[w];  bh[nt][1] = Wh32[w + 4];
                bl[nt][0] = Wl32[w];  bl[nt][1] = Wl32[w + 4];
            }
            #pragma unroll
            for (int mt = 0; mt < 4; mt++)
                #pragma unroll
                for (int nt = 0; nt < 4; nt++) {
                    mma_bf16(acc[mt][nt], ah[mt][0], ah[mt][1], ah[mt][2], ah[mt][3],
                             bh[nt][0], bh[nt][1]);
                    mma_bf16(acc[mt][nt], ah[mt][0], ah[mt][1], ah[mt][2], ah[mt][3],
                             bl[nt][0], bl[nt][1]);
                    mma_bf16(acc[mt][nt], al[mt][0], al[mt][1], al[mt][2], al[mt][3],
                             bh[nt][0], bh[nt][1]);
                }
        }
    }

    #pragma unroll
    for (int mt = 0; mt < 4; mt++) {
        int m = m0 + warpM*64 + mt*16 + lr;
        #pragma unroll
        for (int nt = 0; nt < 4; nt++) {
            int n = n0 + warpN*32 + nt*8 + 2*c;
            float b0v = __ldg(&bias[n]);
            float b1v = __ldg(&bias[n+1]);
            float v0 = acc[mt][nt][0] + b0v;
            float v1 = acc[mt][nt][1] + b1v;
            float v2 = acc[mt][nt][2] + b0v;
            float v3 = acc[mt][nt][3] + b1v;
            if (HEADSPLIT) {
                int b    = m / NSEQ;              // tile never crosses batch
                int nn   = m - b*NSEQ;
                int head = n >> 6;
                int hd0  = n & 63;
                size_t base = (((size_t)(b*NH + head))*NSEQ + nn)*HD + hd0;
                *(float2*)&out[base]        = make_float2(v0, v1);
                *(float2*)&out[base + 8*HD] = make_float2(v2, v3);  // m+8
            } else {
                *(float2*)&out[(size_t)m*BDIM + n]     = make_float2(v0, v1);
                *(float2*)&out[(size_t)(m+8)*BDIM + n] = make_float2(v2, v3);
            }
        }
    }
}

// =============================================================================
// 2D RoPE, out-of-place (verified round 4, kept verbatim).
// =============================================================================
__global__ void rope2_kernel(const float* __restrict__ src,
                             float* __restrict__ dst)
{
    const int total = NB*NH*NSEQ*32;
    int idx = blockIdx.x * blockDim.x + threadIdx.x;
    if (idx >= total) return;

    int j   = idx % 16;
    int r   = idx / 16;
    int seg = r % 2;
    int t   = r / 2;                 // (b*NH+h)*NSEQ + n
    int n   = t % NSEQ;
    int hpos = n / HPATCH;
    int wpos = n - hpos * HPATCH;

    float pos  = (seg == 0) ? (float)hpos : (float)wpos;
    float freq = powf(10000.0f, -(float)j / 16.0f);
    float ang  = pos * freq;
    float cc = cosf(ang);
    float ss = sinf(ang);

    size_t b0 = (size_t)t * HD + seg * 32 + j;
    float x1 = src[b0];
    float x2 = src[b0 + 16];
    dst[b0]      = x1 * cc - x2 * ss;
    dst[b0 + 16] = x1 * ss + x2 * cc;
}

// =============================================================================
// Flash attention (bf16x3 mma, log2-domain online softmax). VERBATIM round 7.
// =============================================================================
#define FW 36            // row stride in words for K / V^T / staged Q
#define QSC  0.18033688011112042f   // 0.125 * log2(e)

__global__ __launch_bounds__(256)
void flash_kernel()
{
    __shared__ __nv_bfloat16 smem[4 * 64 * 72];    // 36864 B
    __nv_bfloat16* Ksh = smem;                     // 64 rows * 72
    __nv_bfloat16* Ksl = Ksh + 64*72;
    __nv_bfloat16* Vsh = Ksl + 64*72;              // 64 d-rows * 72
    __nv_bfloat16* Vsl = Vsh + 64*72;
    uint32_t* Ksh32 = (uint32_t*)Ksh;  uint32_t* Ksl32 = (uint32_t*)Ksl;
    uint32_t* Vsh32 = (uint32_t*)Vsh;  uint32_t* Vsl32 = (uint32_t*)Vsl;

    const int tid  = threadIdx.x;
    const int lane = tid & 31;
    const int wid  = tid >> 5;
    const int c    = lane & 3;
    const int lr   = lane >> 2;
    const int q0   = blockIdx.x * 128;
    const int bh   = blockIdx.y;

    const float* qp = g_q2 + (size_t)bh * NSEQ * HD;
    const float* kp = g_k2 + (size_t)bh * NSEQ * HD;
    const float* vp = g_v  + (size_t)bh * NSEQ * HD;

    // ---- stage Q (hi in first half of smem, lo in second half), stride FW
    uint32_t* Qh32 = (uint32_t*)smem;              // 128*36 words = 18432 B
    uint32_t* Ql32 = Qh32 + 128*FW;                // next 18432 B
    #pragma unroll
    for (int s = 0; s < 8; s++) {
        int idx = tid + s*256;                 // 0..2047 float4 ids (128 x 16)
        int r   = idx >> 4;
        int dq  = (idx & 15) * 4;
        float4 qv = *(const float4*)&qp[(size_t)(q0+r)*HD + dq];
        int w0 = r*FW + (dq >> 1);
        Qh32[w0    ] = pack2(qv.x, qv.y);
        Qh32[w0 + 1] = pack2(qv.z, qv.w);
        Ql32[w0    ] = pack2(lo_of(qv.x), lo_of(qv.y));
        Ql32[w0 + 1] = pack2(lo_of(qv.z), lo_of(qv.w));
    }
    __syncthreads();

    // ---- load Q fragments (warp wid owns rows wid*16 .. +15)
    uint32_t qh[4][4], ql[4][4];
    {
        int rA = wid*16 + lr;
        #pragma unroll
        for (int kt = 0; kt < 4; kt++) {
            int w = rA*FW + kt*8 + c;
            qh[kt][0] = Qh32[w];      qh[kt][1] = Qh32[w + 8*FW];
            qh[kt][2] = Qh32[w + 4];  qh[kt][3] = Qh32[w + 8*FW + 4];
            ql[kt][0] = Ql32[w];      ql[kt][1] = Ql32[w + 8*FW];
            ql[kt][2] = Ql32[w + 4];  ql[kt][3] = Ql32[w + 8*FW + 4];
        }
    }
    __syncthreads();

    float m0r = -__int_as_float(0x7f800000), m1r = m0r;   // -inf (log2 units)
    float l0 = 0.f, l1 = 0.f;
    float O[8][4];
    #pragma unroll
    for (int dt = 0; dt < 8; dt++)
        #pragma unroll
        for (int j = 0; j < 4; j++) O[dt][j] = 0.f;

    for (int kv0 = 0; kv0 < NSEQ; kv0 += 64) {
        // ---- load K (row-major) and V (transposed), hi+lo splits
        #pragma unroll
        for (int s = 0; s < 4; s++) {
            int idx = tid + s*256;             // 0..1023 float4 ids (64 x 16)
            int kv  = idx >> 4;
            int dq  = (idx & 15) * 4;
            float4 kvv = *(const float4*)&kp[(size_t)(kv0+kv)*HD + dq];
            int w0 = kv*FW + (dq >> 1);
            Ksh32[w0    ] = pack2(kvv.x, kvv.y);
            Ksh32[w0 + 1] = pack2(kvv.z, kvv.w);
            Ksl32[w0    ] = pack2(lo_of(kvv.x), lo_of(kvv.y));
            Ksl32[w0 + 1] = pack2(lo_of(kvv.z), lo_of(kvv.w));
            float4 vv = *(const float4*)&vp[(size_t)(kv0+kv)*HD + dq];
            float vf[4] = {vv.x, vv.y, vv.z, vv.w};
            #pragma unroll
            for (int j = 0; j < 4; j++) {
                Vsh[(dq+j)*72 + kv] = __float2bfloat16_rn(vf[j]);
                Vsl[(dq+j)*72 + kv] = __float2bfloat16_rn(lo_of(vf[j]));
            }
        }
        __syncthreads();

        // ---- S = Q K^T (bf16x3), fp32 accum
        float sacc[8][4];
        #pragma unroll
        for (int nt = 0; nt < 8; nt++)
            #pragma unroll
            for (int j = 0; j < 4; j++) sacc[nt][j] = 0.f;

        #pragma unroll
        for (int kt = 0; kt < 4; kt++) {
            #pragma unroll
            for (int nt = 0; nt < 8; nt++) {
                int nB = nt*8 + lr;
                int w  = nB*FW + kt*8 + c;
                uint32_t kb0 = Ksh32[w], kb1 = Ksh32[w + 4];
                uint32_t lb0 = Ksl32[w], lb1 = Ksl32[w + 4];
                mma_bf16(sacc[nt], qh[kt][0], qh[kt][1], qh[kt][2], qh[kt][3], kb0, kb1);
                mma_bf16(sacc[nt], qh[kt][0], qh[kt][1], qh[kt][2], qh[kt][3], lb0, lb1);
                mma_bf16(sacc[nt], ql[kt][0], ql[kt][1], ql[kt][2], ql[kt][3], kb0, kb1);
            }
        }

        // ---- scale to log2 units
        #pragma unroll
        for (int nt = 0; nt < 8; nt++)
            #pragma unroll
            for (int j = 0; j < 4; j++) sacc[nt][j] *= QSC;

        // ---- online softmax (rows r=lr and r+8; quad = lanes sharing lr)
        float mx0 = -__int_as_float(0x7f800000), mx1 = mx0;
        #pragma unroll
        for (int nt = 0; nt < 8; nt++) {
            mx0 = fmaxf(mx0, fmaxf(sacc[nt][0], sacc[nt][1]));
            mx1 = fmaxf(mx1, fmaxf(sacc[nt][2], sacc[nt][3]));
        }
        mx0 = fmaxf(mx0, __shfl_xor_sync(0xffffffffu, mx0, 1));
        mx0 = fmaxf(mx0, __shfl_xor_sync(0xffffffffu, mx0, 2));
        mx1 = fmaxf(mx1, __shfl_xor_sync(0xffffffffu, mx1, 1));
        mx1 = fmaxf(mx1, __shfl_xor_sync(0xffffffffu, mx1, 2));

        float mn0 = fmaxf(m0r, mx0);
        float mn1 = fmaxf(m1r, mx1);
        float cr0 = ex2_approx(m0r - mn0);
        float cr1 = ex2_approx(m1r - mn1);
        m0r = mn0; m1r = mn1;

        float rs0 = 0.f, rs1 = 0.f;
        #pragma unroll
        for (int nt = 0; nt < 8; nt++) {
            sacc[nt][0] = ex2_approx(sacc[nt][0] - mn0);
            sacc[nt][1] = ex2_approx(sacc[nt][1] - mn0);
            sacc[nt][2] = ex2_approx(sacc[nt][2] - mn1);
            sacc[nt][3] = ex2_approx(sacc[nt][3] - mn1);
            rs0 += sacc[nt][0] + sacc[nt][1];
            rs1 += sacc[nt][2] + sacc[nt][3];
        }
        rs0 += __shfl_xor_sync(0xffffffffu, rs0, 1);
        rs0 += __shfl_xor_sync(0xffffffffu, rs0, 2);
        rs1 += __shfl_xor_sync(0xffffffffu, rs1, 1);
        rs1 += __shfl_xor_sync(0xffffffffu, rs1, 2);
        l0 = l0 * cr0 + rs0;
        l1 = l1 * cr1 + rs1;

        #pragma unroll
        for (int dt = 0; dt < 8; dt++) {
            O[dt][0] *= cr0; O[dt][1] *= cr0;
            O[dt][2] *= cr1; O[dt][3] *= cr1;
        }

        // ---- O += P V (bf16x3); P from registers (S nt=2kt,2kt+1 -> A-frag kt)
        #pragma unroll
        for (int kt = 0; kt < 4; kt++) {
            uint32_t pa[4], pl[4];
            pa[0] = pack2(sacc[2*kt][0],   sacc[2*kt][1]);
            pa[1] = pack2(sacc[2*kt][2],   sacc[2*kt][3]);
            pa[2] = pack2(sacc[2*kt+1][0], sacc[2*kt+1][1]);
            pa[3] = pack2(sacc[2*kt+1][2], sacc[2*kt+1][3]);
            pl[0] = pack2(lo_of(sacc[2*kt][0]),   lo_of(sacc[2*kt][1]));
            pl[1] = pack2(lo_of(sacc[2*kt][2]),   lo_of(sacc[2*kt][3]));
            pl[2] = pack2(lo_of(sacc[2*kt+1][0]), lo_of(sacc[2*kt+1][1]));
            pl[3] = pack2(lo_of(sacc[2*kt+1][2]), lo_of(sacc[2*kt+1][3]));
            #pragma unroll
            for (int dt = 0; dt < 8; dt++) {
                int w = (dt*8 + lr)*FW + kt*8 + c;
                uint32_t vb0 = Vsh32[w], vb1 = Vsh32[w + 4];
                uint32_t wl0 = Vsl32[w], wl1 = Vsl32[w + 4];
                mma_bf16(O[dt], pa[0], pa[1], pa[2], pa[3], vb0, vb1);
                mma_bf16(O[dt], pa[0], pa[1], pa[2], pa[3], wl0, wl1);
                mma_bf16(O[dt], pl[0], pl[1], pl[2], pl[3], vb0, vb1);
            }
        }
        __syncthreads();
    }

    // ---- finalize: /= l, write to g_attn [b, n, h*64 + d]
    const int b = bh >> 4;
    const int h = bh & 15;
    float inv0 = 1.0f / l0;
    float inv1 = 1.0f / l1;
    int row0 = q0 + wid*16 + lr;
    #pragma unroll
    for (int dt = 0; dt < 8; dt++) {
        int d = dt*8 + 2*c;
        size_t r0 = ((size_t)(b*NSEQ + row0))*BDIM + h*HD + d;
        *(float2*)&g_attn[r0]           = make_float2(O[dt][0]*inv0, O[dt][1]*inv0);
        *(float2*)&g_attn[r0 + 8*BDIM]  = make_float2(O[dt][2]*inv1, O[dt][3]*inv1);
    }
}

// =============================================================================
// Launch. Binding: size-classified (order-robust, verified in round 4).
// =============================================================================
extern "C" void kernel_launch(void* const* d_in, const int* in_sizes, int n_in,
                              void* d_out, int out_size)
{
    const float* big[3]  = {0,0,0};
    const float* Ws[4]   = {0,0,0,0};
    const float* bs[4]   = {0,0,0,0};
    int nbig = 0, nW = 0, nb = 0;
    for (int i = 0; i < n_in; i++) {
        int s = in_sizes[i];
        if (s == MROWS*BDIM)      { if (nbig < 3) big[nbig++] = (const float*)d_in[i]; }
        else if (s == BDIM*BDIM)  { if (nW  < 4) Ws[nW++]   = (const float*)d_in[i]; }
        else if (s == BDIM)       { if (nb  < 4) bs[nb++]   = (const float*)d_in[i]; }
    }
    const float* query = big[0];
    const float* key   = big[1];
    const float* value = big[2];
    const float* Wq = Ws[0]; const float* bq = bs[0];
    const float* Wk = Ws[1]; const float* bk = bs[1];
    const float* Wv = Ws[2]; const float* bv = bs[2];
    const float* Wo = Ws[3]; const float* bo = bs[3];

    float *qb, *kb, *vb, *q2b, *k2b, *ab;
    uint32_t *xh, *xl, *wh, *wl;
    cudaGetSymbolAddress((void**)&qb,  g_q);
    cudaGetSymbolAddress((void**)&kb,  g_k);
    cudaGetSymbolAddress((void**)&vb,  g_v);
    cudaGetSymbolAddress((void**)&q2b, g_q2);
    cudaGetSymbolAddress((void**)&k2b, g_k2);
    cudaGetSymbolAddress((void**)&ab,  g_attn);
    cudaGetSymbolAddress((void**)&xh,  g_xh);
    cudaGetSymbolAddress((void**)&xl,  g_xl);
    cudaGetSymbolAddress((void**)&wh,  g_wh);
    cudaGetSymbolAddress((void**)&wl,  g_wl);

    const int n4x = MROWS*BDIM/4;     // 2359296
    const int n4w = BDIM*BDIM/4;      // 262144
    dim3 pg(BDIM/128, MROWS/128);     // (8, 72)

    const uint4* uxh = (const uint4*)xh;
    const uint4* uxl = (const uint4*)xl;
    const uint4* uwh = (const uint4*)wh;
    const uint4* uwl = (const uint4*)wl;

    // Q projection
    split_kernel<<<n4w/256, 256>>>((const float4*)Wq, (uint2*)wh, (uint2*)wl, n4w);
    split_kernel<<<n4x/256, 256>>>((const float4*)query, (uint2*)xh, (uint2*)xl, n4x);
    proj_mma3s<1><<<pg, 256>>>(uxh, uxl, uwh, uwl, bq, qb);
    // K projection
    split_kernel<<<n4w/256, 256>>>((const float4*)Wk, (uint2*)wh, (uint2*)wl, n4w);
    split_kernel<<<n4x/256, 256>>>((const float4*)key, (uint2*)xh, (uint2*)xl, n4x);
    proj_mma3s<1><<<pg, 256>>>(uxh, uxl, uwh, uwl, bk, kb);
    // V projection
    split_kernel<<<n4w/256, 256>>>((const float4*)Wv, (uint2*)wh, (uint2*)wl, n4w);
    split_kernel<<<n4x/256, 256>>>((const float4*)value, (uint2*)xh, (uint2*)xl, n4x);
    proj_mma3s<1><<<pg, 256>>>(uxh, uxl, uwh, uwl, bv, vb);

    const int rtot = NB*NH*NSEQ*32;
    rope2_kernel<<<(rtot + 255)/256, 256>>>(qb, q2b);
    rope2_kernel<<<(rtot + 255)/256, 256>>>(kb, k2b);

    flash_kernel<<<dim3(NSEQ/128, NB*NH), 256>>>();

    // Output projection
    split_kernel<<<n4w/256, 256>>>((const float4*)Wo, (uint2*)wh, (uint2*)wl, n4w);
    split_kernel<<<n4x/256, 256>>>((const float4*)ab, (uint2*)xh, (uint2*)xl, n4x);
    proj_mma3s<0><<<pg, 256>>>(uxh, uxl, uwh, uwl, bo, (float*)d_out);
}